// round 2
// baseline (speedup 1.0000x reference)
#include <cuda_runtime.h>
#include <cstdint>

#define NX 256
#define NU 32
#define NY 32
#define BATCH 16
#define TLEN 8192
#define LCH 64
#define NCH (TLEN / LCH)     // 128 chunks
#define NPAIR (TLEN / 2)     // 4096 t-pairs per batch

typedef unsigned long long u64;

__device__ __forceinline__ u64 pk2(float lo, float hi) {
    u64 r; asm("mov.b64 %0,{%1,%2};" : "=l"(r) : "f"(lo), "f"(hi)); return r;
}
__device__ __forceinline__ void upk2(u64 v, float& lo, float& hi) {
    asm("mov.b64 {%0,%1},%2;" : "=f"(lo), "=f"(hi) : "l"(v));
}
__device__ __forceinline__ u64 ffma2(u64 a, u64 b, u64 c) {
    u64 d; asm("fma.rn.f32x2 %0,%1,%2,%3;" : "=l"(d) : "l"(a), "l"(b), "l"(c)); return d;
}
__device__ __forceinline__ u64 add2(u64 a, u64 b) {
    u64 d; asm("add.rn.f32x2 %0,%1,%2;" : "=l"(d) : "l"(a), "l"(b)); return d;
}

// Persistent device scratch
__device__ float g_Bz[NX * NU];             // [n][j]
__device__ float g_CzT[NX * NY];            // [n][y]
__device__ float g_z0[BATCH * NX];
__device__ float g_lamL[NX];                // lam^LCH
__device__ float g_F[BATCH * NCH * NX];
__device__ float g_S[BATCH * NCH * NX];
__device__ u64   g_V[(size_t)BATCH * NPAIR * NX];  // [b][tpair][n] = {v_t, v_t+1}, 134 MB

// ---------------------------------------------------------------------------
// K0: prep — Bz, CzT, z0, lam^LCH
// ---------------------------------------------------------------------------
__global__ void k_prep(const float* __restrict__ x0, const float* __restrict__ Q,
                       const float* __restrict__ lam, const float* __restrict__ Bm,
                       const float* __restrict__ Cin) {
    int idx = blockIdx.x * blockDim.x + threadIdx.x;
    const int tBz = NX * NU;
    const int tCz = tBz + NY * NX;
    const int tZ0 = tCz + BATCH * NX;
    const int total = tZ0 + NX;
    for (; idx < total; idx += gridDim.x * blockDim.x) {
        if (idx < tBz) {
            int n = idx / NU, uu = idx % NU;
            float s = 0.f;
            for (int k = 0; k < NX; k++) s = fmaf(Q[k * NX + n], Bm[k * NU + uu], s);
            g_Bz[idx] = s;
        } else if (idx < tCz) {
            int i = idx - tBz;
            int yy = i / NX, n = i % NX;
            float s = 0.f;
            for (int k = 0; k < NX; k++) s = fmaf(Cin[yy * NX + k], Q[k * NX + n], s);
            g_CzT[n * NY + yy] = s;
        } else if (idx < tZ0) {
            int i = idx - tCz;
            int b = i / NX, n = i % NX;
            float s = 0.f;
            for (int k = 0; k < NX; k++) s = fmaf(x0[b * NX + k], Q[k * NX + n], s);
            g_z0[i] = s;
        } else {
            int n = idx - tZ0;
            float p = lam[n];
            #pragma unroll
            for (int j = 0; j < 6; j++) p = p * p;   // lam^64
            g_lamL[n] = p;
        }
    }
}

// ---------------------------------------------------------------------------
// K1: v = Bz @ u (FFMA2, t-paired), store g_V, chunk-local final F
// ---------------------------------------------------------------------------
__global__ void __launch_bounds__(256) k_vf(const float* __restrict__ u,
                                            const float* __restrict__ lam) {
    const int c = blockIdx.x, b = blockIdx.y, n = threadIdx.x;
    __shared__ __align__(16) float suT[NU * LCH];   // [j][t ^ ((j&7)<<2)]  8 KB

    // Stage u transposed + swizzled
    const float* ub = u + ((size_t)b * TLEN + (size_t)c * LCH) * NU;
    for (int i = n; i < LCH * NU / 4; i += 256) {
        float4 q = ((const float4*)ub)[i];
        int t = i >> 3, j0 = (i & 7) * 4;
        suT[(j0 + 0) * LCH + (t ^ (((j0 + 0) & 7) << 2))] = q.x;
        suT[(j0 + 1) * LCH + (t ^ (((j0 + 1) & 7) << 2))] = q.y;
        suT[(j0 + 2) * LCH + (t ^ (((j0 + 2) & 7) << 2))] = q.z;
        suT[(j0 + 3) * LCH + (t ^ (((j0 + 3) & 7) << 2))] = q.w;
    }

    u64 bz2[NU];
    #pragma unroll
    for (int j = 0; j < NU; j++) { float v = g_Bz[n * NU + j]; bz2[j] = pk2(v, v); }
    const float lamn = lam[n];
    float z = (c == 0) ? g_z0[b * NX + n] : 0.f;
    __syncthreads();

    u64* Vout = g_V + ((size_t)b * NPAIR + (size_t)c * (LCH / 2)) * NX + n;

    #pragma unroll 2
    for (int tg = 0; tg < LCH / 4; tg++) {
        const int t0 = tg * 4;
        u64 va0 = 0, vb0 = 0, va1 = 0, vb1 = 0;
        #pragma unroll
        for (int j = 0; j < NU; j += 2) {
            ulonglong2 qa = *(const ulonglong2*)&suT[j * LCH + (t0 ^ ((j & 7) << 2))];
            va0 = ffma2(bz2[j], qa.x, va0);
            va1 = ffma2(bz2[j], qa.y, va1);
            ulonglong2 qb = *(const ulonglong2*)&suT[(j + 1) * LCH + (t0 ^ (((j + 1) & 7) << 2))];
            vb0 = ffma2(bz2[j + 1], qb.x, vb0);
            vb1 = ffma2(bz2[j + 1], qb.y, vb1);
        }
        u64 v0 = add2(va0, vb0);
        u64 v1 = add2(va1, vb1);
        Vout[(size_t)(tg * 2 + 0) * NX] = v0;
        Vout[(size_t)(tg * 2 + 1) * NX] = v1;
        float x0v, x1v, x2v, x3v;
        upk2(v0, x0v, x1v); upk2(v1, x2v, x3v);
        z = fmaf(lamn, z, x0v);
        z = fmaf(lamn, z, x1v);
        z = fmaf(lamn, z, x2v);
        z = fmaf(lamn, z, x3v);
    }
    g_F[(b * NCH + c) * NX + n] = z;
}

// ---------------------------------------------------------------------------
// K2: cross-chunk carry scan
// ---------------------------------------------------------------------------
__global__ void __launch_bounds__(256) k_carry() {
    const int b = blockIdx.x, n = threadIdx.x;
    const float lamLn = g_lamL[n];
    float s = 0.f;
    g_S[(b * NCH + 0) * NX + n] = 0.f;
    #pragma unroll 8
    for (int c = 1; c < NCH; c++) {
        s = fmaf(lamLn, s, g_F[(b * NCH + c - 1) * NX + n]);
        g_S[(b * NCH + c) * NX + n] = s;
    }
}

// ---------------------------------------------------------------------------
// K3: scan chunk into transposed smem, then Y = Zprev @ Cz^T + U @ D^T (FFMA2)
// ---------------------------------------------------------------------------
__global__ void __launch_bounds__(256) k_out(const float* __restrict__ u,
                                             const float* __restrict__ lam,
                                             const float* __restrict__ Dm,
                                             float* __restrict__ y) {
    extern __shared__ __align__(16) float sm[];
    float* ZT  = sm;                    // NX*LCH  = 16384 floats (64 KB)  [n][t^sw(n)]
    float* suT = ZT + NX * LCH;         // NU*LCH  = 2048  floats (8 KB)   [j][t^sw(j)]
    float* sCz = suT + NU * LCH;        // NX*NY   = 8192  floats (32 KB)  [n][y]
    float* sDT = sCz + NX * NY;         // NU*NY   = 1024  floats (4 KB)   [j][y]

    const int c = blockIdx.x, b = blockIdx.y, tid = threadIdx.x;

    // Stage sCz
    for (int i = tid; i < NX * NY / 4; i += 256)
        ((float4*)sCz)[i] = ((const float4*)g_CzT)[i];
    // Stage sDT (transpose of D)
    for (int i = tid; i < NU * NY; i += 256) {
        int j = i / NY, yy = i % NY;
        sDT[i] = Dm[yy * NU + j];
    }
    // Stage u transposed + swizzled
    const float* ub = u + ((size_t)b * TLEN + (size_t)c * LCH) * NU;
    for (int i = tid; i < LCH * NU / 4; i += 256) {
        float4 q = ((const float4*)ub)[i];
        int t = i >> 3, j0 = (i & 7) * 4;
        suT[(j0 + 0) * LCH + (t ^ (((j0 + 0) & 7) << 2))] = q.x;
        suT[(j0 + 1) * LCH + (t ^ (((j0 + 1) & 7) << 2))] = q.y;
        suT[(j0 + 2) * LCH + (t ^ (((j0 + 2) & 7) << 2))] = q.z;
        suT[(j0 + 3) * LCH + (t ^ (((j0 + 3) & 7) << 2))] = q.w;
    }

    // Scan phase: thread = n; read paired v from g_V, write z_prev transposed
    {
        const int n = tid;
        const int sw = (n & 7) << 2;
        const float lamn = lam[n];
        float z = (c == 0) ? g_z0[b * NX + n] : g_S[(b * NCH + c) * NX + n];
        const u64* Vp = g_V + ((size_t)b * NPAIR + (size_t)c * (LCH / 2)) * NX + n;
        float* Zrow = ZT + n * LCH;
        #pragma unroll 8
        for (int p = 0; p < LCH / 2; p++) {
            u64 vv = Vp[(size_t)p * NX];
            float vlo, vhi;
            upk2(vv, vlo, vhi);
            Zrow[(2 * p) ^ sw] = z;
            z = fmaf(lamn, z, vlo);
            Zrow[(2 * p + 1) ^ sw] = z;
            z = fmaf(lamn, z, vhi);
        }
    }
    __syncthreads();

    // Projection: warp w owns 8 timesteps, lane = y
    const int w = tid >> 5, lane = tid & 31;
    const int t0 = w * 8;

    u64 accA[4] = {0, 0, 0, 0};   // even-k partials
    u64 accB[4] = {0, 0, 0, 0};   // odd-k partials

    for (int n0 = 0; n0 < NX; n0 += 8) {
        const float* Zb = ZT + n0 * LCH;
        const float* Cb = sCz + n0 * NY + lane;
        #pragma unroll
        for (int k = 0; k < 8; k++) {
            const int sw = (k & 7) << 2;   // (n0+k)&7 == k since n0 % 8 == 0
            float cv = Cb[k * NY];
            u64 c2 = pk2(cv, cv);
            ulonglong2 qa = *(const ulonglong2*)&Zb[k * LCH + (t0 ^ sw)];
            ulonglong2 qb = *(const ulonglong2*)&Zb[k * LCH + ((t0 + 4) ^ sw)];
            if (k & 1) {
                accB[0] = ffma2(c2, qa.x, accB[0]);
                accB[1] = ffma2(c2, qa.y, accB[1]);
                accB[2] = ffma2(c2, qb.x, accB[2]);
                accB[3] = ffma2(c2, qb.y, accB[3]);
            } else {
                accA[0] = ffma2(c2, qa.x, accA[0]);
                accA[1] = ffma2(c2, qa.y, accA[1]);
                accA[2] = ffma2(c2, qb.x, accA[2]);
                accA[3] = ffma2(c2, qb.y, accA[3]);
            }
        }
    }

    // D-term
    #pragma unroll
    for (int j = 0; j < NU; j++) {
        const int sw = (j & 7) << 2;
        float dv = sDT[j * NY + lane];
        u64 d2 = pk2(dv, dv);
        ulonglong2 qa = *(const ulonglong2*)&suT[j * LCH + (t0 ^ sw)];
        ulonglong2 qb = *(const ulonglong2*)&suT[j * LCH + ((t0 + 4) ^ sw)];
        if (j & 1) {
            accB[0] = ffma2(d2, qa.x, accB[0]);
            accB[1] = ffma2(d2, qa.y, accB[1]);
            accB[2] = ffma2(d2, qb.x, accB[2]);
            accB[3] = ffma2(d2, qb.y, accB[3]);
        } else {
            accA[0] = ffma2(d2, qa.x, accA[0]);
            accA[1] = ffma2(d2, qa.y, accA[1]);
            accA[2] = ffma2(d2, qb.x, accA[2]);
            accA[3] = ffma2(d2, qb.y, accA[3]);
        }
    }

    // Store y
    float* yb = y + ((size_t)(b * TLEN + c * LCH + t0)) * NY + lane;
    #pragma unroll
    for (int g = 0; g < 4; g++) {
        u64 s = add2(accA[g], accB[g]);
        float o0, o1;
        upk2(s, o0, o1);
        yb[(size_t)(2 * g) * NY] = o0;
        yb[(size_t)(2 * g + 1) * NY] = o1;
    }
}

// ---------------------------------------------------------------------------
extern "C" void kernel_launch(void* const* d_in, const int* in_sizes, int n_in,
                              void* d_out, int out_size) {
    const float* x0  = (const float*)d_in[0];
    const float* u   = (const float*)d_in[1];
    const float* Q   = (const float*)d_in[2];
    const float* lam = (const float*)d_in[3];
    const float* Bm  = (const float*)d_in[4];
    const float* Cin = (const float*)d_in[5];
    const float* Dm  = (const float*)d_in[6];
    float* y = (float*)d_out;

    const int smem_k3 = (NX * LCH + NU * LCH + NX * NY + NU * NY) * 4;  // 110592 B
    cudaFuncSetAttribute(k_out, cudaFuncAttributeMaxDynamicSharedMemorySize, smem_k3);

    k_prep<<<82, 256>>>(x0, Q, lam, Bm, Cin);
    k_vf<<<dim3(NCH, BATCH), 256>>>(u, lam);
    k_carry<<<BATCH, 256>>>();
    k_out<<<dim3(NCH, BATCH), 256, smem_k3>>>(u, lam, Dm, y);
}

// round 3
// speedup vs baseline: 1.0107x; 1.0107x over previous
#include <cuda_runtime.h>
#include <cstdint>

#define NX 256
#define NU 32
#define NY 32
#define BATCH 16
#define TLEN 8192
#define LCH 64
#define NCH (TLEN / LCH)     // 128 chunks
#define NPAIR (TLEN / 2)     // 4096 t-pairs per batch

typedef unsigned long long u64;

__device__ __forceinline__ u64 pk2(float lo, float hi) {
    u64 r; asm("mov.b64 %0,{%1,%2};" : "=l"(r) : "f"(lo), "f"(hi)); return r;
}
__device__ __forceinline__ void upk2(u64 v, float& lo, float& hi) {
    asm("mov.b64 {%0,%1},%2;" : "=f"(lo), "=f"(hi) : "l"(v));
}
__device__ __forceinline__ u64 ffma2(u64 a, u64 b, u64 c) {
    u64 d; asm("fma.rn.f32x2 %0,%1,%2,%3;" : "=l"(d) : "l"(a), "l"(b), "l"(c)); return d;
}
__device__ __forceinline__ u64 add2(u64 a, u64 b) {
    u64 d; asm("add.rn.f32x2 %0,%1,%2;" : "=l"(d) : "l"(a), "l"(b)); return d;
}

// Persistent device scratch
__device__ float g_Bz[NX * NU];             // [n][j]
__device__ float g_CzT[NX * NY];            // [n][y]
__device__ float g_z0[BATCH * NX];
__device__ float g_lamL[NX];                // lam^LCH
__device__ float g_F[BATCH * NCH * NX];
__device__ float g_S[BATCH * NCH * NX];
__device__ u64   g_V[(size_t)BATCH * NPAIR * NX];  // [b][tpair][n] = {v_t, v_t+1}, 134 MB

// ---------------------------------------------------------------------------
// K0: prep — Bz, CzT, z0, lam^LCH
// ---------------------------------------------------------------------------
__global__ void k_prep(const float* __restrict__ x0, const float* __restrict__ Q,
                       const float* __restrict__ lam, const float* __restrict__ Bm,
                       const float* __restrict__ Cin) {
    int idx = blockIdx.x * blockDim.x + threadIdx.x;
    const int tBz = NX * NU;
    const int tCz = tBz + NY * NX;
    const int tZ0 = tCz + BATCH * NX;
    const int total = tZ0 + NX;
    for (; idx < total; idx += gridDim.x * blockDim.x) {
        if (idx < tBz) {
            int n = idx / NU, uu = idx % NU;
            float s = 0.f;
            for (int k = 0; k < NX; k++) s = fmaf(Q[k * NX + n], Bm[k * NU + uu], s);
            g_Bz[idx] = s;
        } else if (idx < tCz) {
            int i = idx - tBz;
            int yy = i / NX, n = i % NX;
            float s = 0.f;
            for (int k = 0; k < NX; k++) s = fmaf(Cin[yy * NX + k], Q[k * NX + n], s);
            g_CzT[n * NY + yy] = s;
        } else if (idx < tZ0) {
            int i = idx - tCz;
            int b = i / NX, n = i % NX;
            float s = 0.f;
            for (int k = 0; k < NX; k++) s = fmaf(x0[b * NX + k], Q[k * NX + n], s);
            g_z0[i] = s;
        } else {
            int n = idx - tZ0;
            float p = lam[n];
            #pragma unroll
            for (int j = 0; j < 6; j++) p = p * p;   // lam^64
            g_lamL[n] = p;
        }
    }
}

// ---------------------------------------------------------------------------
// K1: v = Bz @ u (FFMA2, t-paired), store g_V, chunk-local final F
// ---------------------------------------------------------------------------
__global__ void __launch_bounds__(256) k_vf(const float* __restrict__ u,
                                            const float* __restrict__ lam) {
    const int c = blockIdx.x, b = blockIdx.y, n = threadIdx.x;
    __shared__ __align__(16) float suT[NU * LCH];   // [j][t ^ ((j&7)<<2)]  8 KB

    // Stage u transposed + swizzled
    const float* ub = u + ((size_t)b * TLEN + (size_t)c * LCH) * NU;
    for (int i = n; i < LCH * NU / 4; i += 256) {
        float4 q = ((const float4*)ub)[i];
        int t = i >> 3, j0 = (i & 7) * 4;
        suT[(j0 + 0) * LCH + (t ^ (((j0 + 0) & 7) << 2))] = q.x;
        suT[(j0 + 1) * LCH + (t ^ (((j0 + 1) & 7) << 2))] = q.y;
        suT[(j0 + 2) * LCH + (t ^ (((j0 + 2) & 7) << 2))] = q.z;
        suT[(j0 + 3) * LCH + (t ^ (((j0 + 3) & 7) << 2))] = q.w;
    }

    u64 bz2[NU];
    #pragma unroll
    for (int j = 0; j < NU; j++) { float v = g_Bz[n * NU + j]; bz2[j] = pk2(v, v); }
    const float lamn = lam[n];
    float z = (c == 0) ? g_z0[b * NX + n] : 0.f;
    __syncthreads();

    u64* Vout = g_V + ((size_t)b * NPAIR + (size_t)c * (LCH / 2)) * NX + n;

    #pragma unroll 2
    for (int tg = 0; tg < LCH / 4; tg++) {
        const int t0 = tg * 4;
        u64 va0 = 0, vb0 = 0, va1 = 0, vb1 = 0;
        #pragma unroll
        for (int j = 0; j < NU; j += 2) {
            ulonglong2 qa = *(const ulonglong2*)&suT[j * LCH + (t0 ^ ((j & 7) << 2))];
            va0 = ffma2(bz2[j], qa.x, va0);
            va1 = ffma2(bz2[j], qa.y, va1);
            ulonglong2 qb = *(const ulonglong2*)&suT[(j + 1) * LCH + (t0 ^ (((j + 1) & 7) << 2))];
            vb0 = ffma2(bz2[j + 1], qb.x, vb0);
            vb1 = ffma2(bz2[j + 1], qb.y, vb1);
        }
        u64 v0 = add2(va0, vb0);
        u64 v1 = add2(va1, vb1);
        Vout[(size_t)(tg * 2 + 0) * NX] = v0;
        Vout[(size_t)(tg * 2 + 1) * NX] = v1;
        float x0v, x1v, x2v, x3v;
        upk2(v0, x0v, x1v); upk2(v1, x2v, x3v);
        z = fmaf(lamn, z, x0v);
        z = fmaf(lamn, z, x1v);
        z = fmaf(lamn, z, x2v);
        z = fmaf(lamn, z, x3v);
    }
    g_F[(b * NCH + c) * NX + n] = z;
}

// ---------------------------------------------------------------------------
// K2: cross-chunk carry scan
// ---------------------------------------------------------------------------
__global__ void __launch_bounds__(256) k_carry() {
    const int b = blockIdx.x, n = threadIdx.x;
    const float lamLn = g_lamL[n];
    float s = 0.f;
    g_S[(b * NCH + 0) * NX + n] = 0.f;
    #pragma unroll 8
    for (int c = 1; c < NCH; c++) {
        s = fmaf(lamLn, s, g_F[(b * NCH + c - 1) * NX + n]);
        g_S[(b * NCH + c) * NX + n] = s;
    }
}

// ---------------------------------------------------------------------------
// K3: scan chunk into transposed smem, then Y = Zprev @ Cz^T + U @ D^T (FFMA2)
// ---------------------------------------------------------------------------
__global__ void __launch_bounds__(256) k_out(const float* __restrict__ u,
                                             const float* __restrict__ lam,
                                             const float* __restrict__ Dm,
                                             float* __restrict__ y) {
    extern __shared__ __align__(16) float sm[];
    float* ZT  = sm;                    // NX*LCH  = 16384 floats (64 KB)  [n][t^sw(n)]
    float* suT = ZT + NX * LCH;         // NU*LCH  = 2048  floats (8 KB)   [j][t^sw(j)]
    float* sCz = suT + NU * LCH;        // NX*NY   = 8192  floats (32 KB)  [n][y]
    float* sDT = sCz + NX * NY;         // NU*NY   = 1024  floats (4 KB)   [j][y]

    const int c = blockIdx.x, b = blockIdx.y, tid = threadIdx.x;

    // Stage sCz
    for (int i = tid; i < NX * NY / 4; i += 256)
        ((float4*)sCz)[i] = ((const float4*)g_CzT)[i];
    // Stage sDT (transpose of D)
    for (int i = tid; i < NU * NY; i += 256) {
        int j = i / NY, yy = i % NY;
        sDT[i] = Dm[yy * NU + j];
    }
    // Stage u transposed + swizzled
    const float* ub = u + ((size_t)b * TLEN + (size_t)c * LCH) * NU;
    for (int i = tid; i < LCH * NU / 4; i += 256) {
        float4 q = ((const float4*)ub)[i];
        int t = i >> 3, j0 = (i & 7) * 4;
        suT[(j0 + 0) * LCH + (t ^ (((j0 + 0) & 7) << 2))] = q.x;
        suT[(j0 + 1) * LCH + (t ^ (((j0 + 1) & 7) << 2))] = q.y;
        suT[(j0 + 2) * LCH + (t ^ (((j0 + 2) & 7) << 2))] = q.z;
        suT[(j0 + 3) * LCH + (t ^ (((j0 + 3) & 7) << 2))] = q.w;
    }

    // Scan phase: thread = n; read paired v from g_V, write z_prev transposed
    {
        const int n = tid;
        const int sw = (n & 7) << 2;
        const float lamn = lam[n];
        float z = (c == 0) ? g_z0[b * NX + n] : g_S[(b * NCH + c) * NX + n];
        const u64* Vp = g_V + ((size_t)b * NPAIR + (size_t)c * (LCH / 2)) * NX + n;
        float* Zrow = ZT + n * LCH;
        #pragma unroll 8
        for (int p = 0; p < LCH / 2; p++) {
            u64 vv = Vp[(size_t)p * NX];
            float vlo, vhi;
            upk2(vv, vlo, vhi);
            Zrow[(2 * p) ^ sw] = z;
            z = fmaf(lamn, z, vlo);
            Zrow[(2 * p + 1) ^ sw] = z;
            z = fmaf(lamn, z, vhi);
        }
    }
    __syncthreads();

    // Projection: warp w owns 8 timesteps, lane = y
    const int w = tid >> 5, lane = tid & 31;
    const int t0 = w * 8;

    u64 accA[4] = {0, 0, 0, 0};   // even-k partials
    u64 accB[4] = {0, 0, 0, 0};   // odd-k partials

    for (int n0 = 0; n0 < NX; n0 += 8) {
        const float* Zb = ZT + n0 * LCH;
        const float* Cb = sCz + n0 * NY + lane;
        #pragma unroll
        for (int k = 0; k < 8; k++) {
            const int sw = (k & 7) << 2;   // (n0+k)&7 == k since n0 % 8 == 0
            float cv = Cb[k * NY];
            u64 c2 = pk2(cv, cv);
            ulonglong2 qa = *(const ulonglong2*)&Zb[k * LCH + (t0 ^ sw)];
            ulonglong2 qb = *(const ulonglong2*)&Zb[k * LCH + ((t0 + 4) ^ sw)];
            if (k & 1) {
                accB[0] = ffma2(c2, qa.x, accB[0]);
                accB[1] = ffma2(c2, qa.y, accB[1]);
                accB[2] = ffma2(c2, qb.x, accB[2]);
                accB[3] = ffma2(c2, qb.y, accB[3]);
            } else {
                accA[0] = ffma2(c2, qa.x, accA[0]);
                accA[1] = ffma2(c2, qa.y, accA[1]);
                accA[2] = ffma2(c2, qb.x, accA[2]);
                accA[3] = ffma2(c2, qb.y, accA[3]);
            }
        }
    }

    // D-term
    #pragma unroll
    for (int j = 0; j < NU; j++) {
        const int sw = (j & 7) << 2;
        float dv = sDT[j * NY + lane];
        u64 d2 = pk2(dv, dv);
        ulonglong2 qa = *(const ulonglong2*)&suT[j * LCH + (t0 ^ sw)];
        ulonglong2 qb = *(const ulonglong2*)&suT[j * LCH + ((t0 + 4) ^ sw)];
        if (j & 1) {
            accB[0] = ffma2(d2, qa.x, accB[0]);
            accB[1] = ffma2(d2, qa.y, accB[1]);
            accB[2] = ffma2(d2, qb.x, accB[2]);
            accB[3] = ffma2(d2, qb.y, accB[3]);
        } else {
            accA[0] = ffma2(d2, qa.x, accA[0]);
            accA[1] = ffma2(d2, qa.y, accA[1]);
            accA[2] = ffma2(d2, qb.x, accA[2]);
            accA[3] = ffma2(d2, qb.y, accA[3]);
        }
    }

    // Store y
    float* yb = y + ((size_t)(b * TLEN + c * LCH + t0)) * NY + lane;
    #pragma unroll
    for (int g = 0; g < 4; g++) {
        u64 s = add2(accA[g], accB[g]);
        float o0, o1;
        upk2(s, o0, o1);
        yb[(size_t)(2 * g) * NY] = o0;
        yb[(size_t)(2 * g + 1) * NY] = o1;
    }
}

// ---------------------------------------------------------------------------
extern "C" void kernel_launch(void* const* d_in, const int* in_sizes, int n_in,
                              void* d_out, int out_size) {
    const float* x0  = (const float*)d_in[0];
    const float* u   = (const float*)d_in[1];
    const float* Q   = (const float*)d_in[2];
    const float* lam = (const float*)d_in[3];
    const float* Bm  = (const float*)d_in[4];
    const float* Cin = (const float*)d_in[5];
    const float* Dm  = (const float*)d_in[6];
    float* y = (float*)d_out;

    const int smem_k3 = (NX * LCH + NU * LCH + NX * NY + NU * NY) * 4;  // 110592 B
    cudaFuncSetAttribute(k_out, cudaFuncAttributeMaxDynamicSharedMemorySize, smem_k3);

    k_prep<<<82, 256>>>(x0, Q, lam, Bm, Cin);
    k_vf<<<dim3(NCH, BATCH), 256>>>(u, lam);
    k_carry<<<BATCH, 256>>>();
    k_out<<<dim3(NCH, BATCH), 256, smem_k3>>>(u, lam, Dm, y);
}